// round 4
// baseline (speedup 1.0000x reference)
#include <cuda_runtime.h>
#include <math.h>

#define N_NODES 100000
#define N_EDGES 800000
#define F 128
#define SCAN_B 1024
#define NB_SCAN ((N_NODES + SCAN_B - 1) / SCAN_B)   // 98

// ---------------- static scratch (allocation-free rule) ----------------
__device__ int   g_deg[N_NODES];
__device__ float g_dinv[N_NODES];
__device__ int   g_off[N_NODES + 1];
__device__ int   g_cursor[N_NODES];
__device__ int   g_src[N_EDGES];
__device__ int   g_bsum[NB_SCAN + 32];
__device__ float g_h1[(size_t)N_NODES * F];
__device__ float g_h2[(size_t)N_NODES * F];

// ---------------- degree count ----------------
__global__ void k_zero_deg() {
    int i = blockIdx.x * blockDim.x + threadIdx.x;
    if (i < N_NODES) g_deg[i] = 0;
}

__global__ void k_count(const int* __restrict__ ei) {
    int e = blockIdx.x * blockDim.x + threadIdx.x;
    if (e < N_EDGES) {
        int col = ei[N_EDGES + e];
        if ((unsigned)col < (unsigned)N_NODES)
            atomicAdd(&g_deg[col], 1);
    }
}

// ---------------- exclusive scan of g_deg -> g_off ----------------
__global__ void k_scan1() {
    __shared__ int s[SCAN_B];
    int i = blockIdx.x * SCAN_B + threadIdx.x;
    int v = (i < N_NODES) ? g_deg[i] : 0;
    s[threadIdx.x] = v;
    __syncthreads();
    for (int off = 1; off < SCAN_B; off <<= 1) {
        int t = 0;
        if (threadIdx.x >= off) t = s[threadIdx.x - off];
        __syncthreads();
        if (threadIdx.x >= off) s[threadIdx.x] += t;
        __syncthreads();
    }
    if (i < N_NODES) g_off[i] = s[threadIdx.x] - v;  // partial exclusive
    if (threadIdx.x == SCAN_B - 1) g_bsum[blockIdx.x] = s[threadIdx.x];
}

__global__ void k_scan2() {
    if (threadIdx.x == 0 && blockIdx.x == 0) {
        int run = 0;
        for (int b = 0; b < NB_SCAN; b++) {
            int t = g_bsum[b];
            g_bsum[b] = run;
            run += t;
        }
    }
}

__global__ void k_scan3() {
    int i = blockIdx.x * blockDim.x + threadIdx.x;
    if (i < N_NODES) {
        int off = g_off[i] + g_bsum[i / SCAN_B];
        g_off[i] = off;
        g_cursor[i] = off;
        // dinv: degree includes self loop (+1)
        g_dinv[i] = rsqrtf((float)(g_deg[i] + 1));
    }
    if (i == 0) g_off[N_NODES] = N_EDGES;
}

// ---------------- place edges into CSR (by destination) ----------------
__global__ void k_place(const int* __restrict__ ei) {
    int e = blockIdx.x * blockDim.x + threadIdx.x;
    if (e < N_EDGES) {
        int row = ei[e];
        int col = ei[N_EDGES + e];
        if ((unsigned)row < (unsigned)N_NODES && (unsigned)col < (unsigned)N_NODES) {
            int pos = atomicAdd(&g_cursor[col], 1);
            if ((unsigned)pos < (unsigned)N_EDGES)
                g_src[pos] = row;
        }
    }
}

// ---------------- one propagation hop (gather form, warp per node) ----------------
__global__ void k_hop(const float* __restrict__ hin, float* __restrict__ hout) {
    int gt   = blockIdx.x * blockDim.x + threadIdx.x;
    int node = gt >> 5;
    int lane = gt & 31;
    if (node >= N_NODES) return;

    float di = g_dinv[node];
    const float4* hin4 = (const float4*)hin;

    // self loop: weight dinv[i]^2 ; edges: dinv[i]*dinv[src]
    float4 v = __ldg(&hin4[(size_t)node * 32 + lane]);
    float4 acc;
    acc.x = di * v.x; acc.y = di * v.y; acc.z = di * v.z; acc.w = di * v.w;

    int s = g_off[node];
    int e = g_off[node + 1];
    for (int k = s; k < e; k++) {
        int src = __ldg(&g_src[k]);
        float w = __ldg(&g_dinv[src]);
        float4 u = __ldg(&hin4[(size_t)src * 32 + lane]);
        acc.x += w * u.x; acc.y += w * u.y; acc.z += w * u.z; acc.w += w * u.w;
    }
    acc.x *= di; acc.y *= di; acc.z *= di; acc.w *= di;
    ((float4*)hout)[(size_t)node * 32 + lane] = acc;
}

// ---------------- GEMM: out = H @ W^T + b ----------------
// H: [N_NODES, 128], W: [128, 128] row-major (out[n][o] = sum_k H[n][k]*W[o][k] + b[o])
#define TM 128
#define TN 128
#define TK 16

__global__ __launch_bounds__(256) void k_gemm(const float* __restrict__ H,
                                              const float* __restrict__ W,
                                              const float* __restrict__ bias,
                                              float* __restrict__ out) {
    __shared__ float sA[TK][TM];   // sA[k][m]
    __shared__ float sB[TK][TN];   // sB[k][n] = W[n][k]

    int tid   = threadIdx.x;
    int m_blk = blockIdx.x * TM;
    int lrow  = tid >> 1;              // 0..127
    int lk0   = (tid & 1) * 8;         // 0 or 8
    int tm0   = (tid >> 4) * 8;        // 0..120
    int tn0   = (tid & 15) * 8;        // 0..120

    float acc[8][8];
#pragma unroll
    for (int i = 0; i < 8; i++)
#pragma unroll
        for (int j = 0; j < 8; j++) acc[i][j] = 0.0f;

    for (int kc = 0; kc < F; kc += TK) {
        // load A slice (rows of H, guarded) and B slice (rows of W)
        float4 a0 = {0,0,0,0}, a1 = {0,0,0,0};
        int gm = m_blk + lrow;
        if (gm < N_NODES) {
            const float4* p = (const float4*)(H + (size_t)gm * F + kc + lk0);
            a0 = p[0]; a1 = p[1];
        }
        const float4* q = (const float4*)(W + (size_t)lrow * F + kc + lk0);
        float4 b0 = q[0], b1 = q[1];

        __syncthreads();   // previous tile's compute done
        sA[lk0 + 0][lrow] = a0.x; sA[lk0 + 1][lrow] = a0.y;
        sA[lk0 + 2][lrow] = a0.z; sA[lk0 + 3][lrow] = a0.w;
        sA[lk0 + 4][lrow] = a1.x; sA[lk0 + 5][lrow] = a1.y;
        sA[lk0 + 6][lrow] = a1.z; sA[lk0 + 7][lrow] = a1.w;
        sB[lk0 + 0][lrow] = b0.x; sB[lk0 + 1][lrow] = b0.y;
        sB[lk0 + 2][lrow] = b0.z; sB[lk0 + 3][lrow] = b0.w;
        sB[lk0 + 4][lrow] = b1.x; sB[lk0 + 5][lrow] = b1.y;
        sB[lk0 + 6][lrow] = b1.z; sB[lk0 + 7][lrow] = b1.w;
        __syncthreads();

#pragma unroll
        for (int kk = 0; kk < TK; kk++) {
            float4 av0 = *(const float4*)&sA[kk][tm0];
            float4 av1 = *(const float4*)&sA[kk][tm0 + 4];
            float4 bv0 = *(const float4*)&sB[kk][tn0];
            float4 bv1 = *(const float4*)&sB[kk][tn0 + 4];
            float a[8] = {av0.x, av0.y, av0.z, av0.w, av1.x, av1.y, av1.z, av1.w};
            float b[8] = {bv0.x, bv0.y, bv0.z, bv0.w, bv1.x, bv1.y, bv1.z, bv1.w};
#pragma unroll
            for (int i = 0; i < 8; i++)
#pragma unroll
                for (int j = 0; j < 8; j++) acc[i][j] += a[i] * b[j];
        }
    }

    float bj[8];
#pragma unroll
    for (int j = 0; j < 8; j++) bj[j] = __ldg(&bias[tn0 + j]);

#pragma unroll
    for (int i = 0; i < 8; i++) {
        int gm = m_blk + tm0 + i;
        if (gm < N_NODES) {
            float4 o0, o1;
            o0.x = acc[i][0] + bj[0]; o0.y = acc[i][1] + bj[1];
            o0.z = acc[i][2] + bj[2]; o0.w = acc[i][3] + bj[3];
            o1.x = acc[i][4] + bj[4]; o1.y = acc[i][5] + bj[5];
            o1.z = acc[i][6] + bj[6]; o1.w = acc[i][7] + bj[7];
            float* op = out + (size_t)gm * F + tn0;
            ((float4*)op)[0] = o0;
            ((float4*)op)[1] = o1;
        }
    }
}

// ---------------- in-place log_softmax over dim 1, warp per node ----------------
__global__ void k_lsm(float* __restrict__ out) {
    int gt   = blockIdx.x * blockDim.x + threadIdx.x;
    int node = gt >> 5;
    int lane = gt & 31;
    if (node >= N_NODES) return;

    float4* p = (float4*)(out + (size_t)node * F);
    float4 v = p[lane];

    float m = fmaxf(fmaxf(v.x, v.y), fmaxf(v.z, v.w));
#pragma unroll
    for (int o = 16; o; o >>= 1) m = fmaxf(m, __shfl_xor_sync(0xFFFFFFFFu, m, o));

    float s = expf(v.x - m) + expf(v.y - m) + expf(v.z - m) + expf(v.w - m);
#pragma unroll
    for (int o = 16; o; o >>= 1) s += __shfl_xor_sync(0xFFFFFFFFu, s, o);

    float l = m + logf(s);
    v.x -= l; v.y -= l; v.z -= l; v.w -= l;
    p[lane] = v;
}

// ---------------- launch ----------------
extern "C" void kernel_launch(void* const* d_in, const int* in_sizes, int n_in,
                              void* d_out, int out_size) {
    const float* x  = (const float*)d_in[0];   // [100000, 128]
    const float* W  = (const float*)d_in[1];   // [128, 128]
    const float* b  = (const float*)d_in[2];   // [128]
    const int*   ei = (const int*)d_in[3];     // [2, 800000] as int32
    float* out = (float*)d_out;

    float* h1; cudaGetSymbolAddress((void**)&h1, g_h1);
    float* h2; cudaGetSymbolAddress((void**)&h2, g_h2);

    const int nodes_b = (N_NODES + 255) / 256;
    const int edges_b = (N_EDGES + 255) / 256;
    const int warp_b  = (N_NODES * 32 + 255) / 256;
    const int gemm_b  = (N_NODES + TM - 1) / TM;

    k_zero_deg<<<nodes_b, 256>>>();
    k_count<<<edges_b, 256>>>(ei);
    k_scan1<<<NB_SCAN, SCAN_B>>>();
    k_scan2<<<1, 32>>>();
    k_scan3<<<nodes_b, 256>>>();
    k_place<<<edges_b, 256>>>(ei);

    k_hop<<<warp_b, 256>>>(x, h1);
    k_hop<<<warp_b, 256>>>(h1, h2);

    k_gemm<<<gemm_b, 256>>>(h2, W, b, out);
    k_lsm<<<warp_b, 256>>>(out);
}

// round 6
// speedup vs baseline: 1.5738x; 1.5738x over previous
#include <cuda_runtime.h>
#include <math.h>

#define N_NODES 100000
#define N_EDGES 800000
#define F 128
#define SCAN_B 1024
#define NB_SCAN ((N_NODES + SCAN_B - 1) / SCAN_B)   // 98

// ---------------- static scratch (allocation-free rule) ----------------
__device__ int   g_deg[N_NODES];
__device__ float g_dinv[N_NODES];
__device__ int   g_off[N_NODES + 1];
__device__ int   g_cursor[N_NODES];
__device__ int   g_src[N_EDGES];
__device__ int   g_bsum[NB_SCAN + 32];
__device__ float g_h1[(size_t)N_NODES * F];
__device__ float g_h2[(size_t)N_NODES * F];

// ---------------- degree count ----------------
__global__ void k_count(const int* __restrict__ ei) {
    int e = blockIdx.x * blockDim.x + threadIdx.x;
    if (e < N_EDGES) {
        int col = ei[N_EDGES + e];
        if ((unsigned)col < (unsigned)N_NODES)
            atomicAdd(&g_deg[col], 1);
    }
}

// ---------------- exclusive scan of g_deg -> g_off ----------------
__global__ void k_scan1() {
    __shared__ int s[SCAN_B];
    int i = blockIdx.x * SCAN_B + threadIdx.x;
    int v = (i < N_NODES) ? g_deg[i] : 0;
    s[threadIdx.x] = v;
    __syncthreads();
    for (int off = 1; off < SCAN_B; off <<= 1) {
        int t = 0;
        if (threadIdx.x >= off) t = s[threadIdx.x - off];
        __syncthreads();
        if (threadIdx.x >= off) s[threadIdx.x] += t;
        __syncthreads();
    }
    if (i < N_NODES) g_off[i] = s[threadIdx.x] - v;  // partial exclusive
    if (threadIdx.x == SCAN_B - 1) g_bsum[blockIdx.x] = s[threadIdx.x];
}

// parallel scan of the 98 block sums (one block, Hillis-Steele)
__global__ void k_scan2() {
    __shared__ int s[128];
    int t = threadIdx.x;
    int v = (t < NB_SCAN) ? g_bsum[t] : 0;
    s[t] = v;
    __syncthreads();
#pragma unroll
    for (int off = 1; off < 128; off <<= 1) {
        int u = 0;
        if (t >= off) u = s[t - off];
        __syncthreads();
        if (t >= off) s[t] += u;
        __syncthreads();
    }
    if (t < NB_SCAN) g_bsum[t] = s[t] - v;  // exclusive
}

__global__ void k_scan3() {
    int i = blockIdx.x * blockDim.x + threadIdx.x;
    if (i < N_NODES) {
        int off = g_off[i] + g_bsum[i / SCAN_B];
        g_off[i] = off;
        g_cursor[i] = off;
        // dinv: degree includes self loop (+1)
        g_dinv[i] = rsqrtf((float)(g_deg[i] + 1));
    }
    if (i == 0) g_off[N_NODES] = N_EDGES;
}

// ---------------- place edges into CSR (by destination) ----------------
__global__ void k_place(const int* __restrict__ ei) {
    int e = blockIdx.x * blockDim.x + threadIdx.x;
    if (e < N_EDGES) {
        int row = ei[e];
        int col = ei[N_EDGES + e];
        if ((unsigned)row < (unsigned)N_NODES && (unsigned)col < (unsigned)N_NODES) {
            int pos = atomicAdd(&g_cursor[col], 1);
            if ((unsigned)pos < (unsigned)N_EDGES)
                g_src[pos] = row;
        }
    }
}

// ---------------- one propagation hop (gather form, warp per node) ----------------
__global__ void k_hop(const float* __restrict__ hin, float* __restrict__ hout) {
    int gt   = blockIdx.x * blockDim.x + threadIdx.x;
    int node = gt >> 5;
    int lane = gt & 31;
    if (node >= N_NODES) return;

    float di = __ldg(&g_dinv[node]);
    const float4* hin4 = (const float4*)hin;

    // self loop: weight dinv[i]^2 ; edges: dinv[i]*dinv[src]
    float4 v = __ldg(&hin4[(size_t)node * 32 + lane]);
    float4 acc;
    acc.x = di * v.x; acc.y = di * v.y; acc.z = di * v.z; acc.w = di * v.w;

    int s = __ldg(&g_off[node]);
    int e = __ldg(&g_off[node + 1]);
    int k = s;
    // 2-wide software pipeline: issue both index loads, both weight loads and
    // both 512B row loads before consuming -> doubles outstanding loads.
    for (; k + 1 < e; k += 2) {
        int s0 = __ldg(&g_src[k]);
        int s1 = __ldg(&g_src[k + 1]);
        float w0 = __ldg(&g_dinv[s0]);
        float w1 = __ldg(&g_dinv[s1]);
        float4 u0 = __ldg(&hin4[(size_t)s0 * 32 + lane]);
        float4 u1 = __ldg(&hin4[(size_t)s1 * 32 + lane]);
        acc.x += w0 * u0.x + w1 * u1.x;
        acc.y += w0 * u0.y + w1 * u1.y;
        acc.z += w0 * u0.z + w1 * u1.z;
        acc.w += w0 * u0.w + w1 * u1.w;
    }
    if (k < e) {
        int s0 = __ldg(&g_src[k]);
        float w0 = __ldg(&g_dinv[s0]);
        float4 u0 = __ldg(&hin4[(size_t)s0 * 32 + lane]);
        acc.x += w0 * u0.x; acc.y += w0 * u0.y;
        acc.z += w0 * u0.z; acc.w += w0 * u0.w;
    }
    acc.x *= di; acc.y *= di; acc.z *= di; acc.w *= di;
    ((float4*)hout)[(size_t)node * 32 + lane] = acc;
}

// ---------------- GEMM + fused log_softmax ----------------
// out[n][o] = log_softmax_o( sum_k H[n][k]*W[o][k] + b[o] )
// TN == F, so each block owns complete output rows; row r=tm0+i is held by the
// 16 consecutive tids with the same tid>>4 (an aligned half-warp) -> shfl.xor
// reduction over offsets 1,2,4,8 gives the row max / sum(exp) in registers.
#define TM 128
#define TN 128
#define TK 16

__global__ __launch_bounds__(256) void k_gemm_lsm(const float* __restrict__ H,
                                                  const float* __restrict__ W,
                                                  const float* __restrict__ bias,
                                                  float* __restrict__ out) {
    __shared__ float sA[TK][TM];   // sA[k][m]
    __shared__ float sB[TK][TN];   // sB[k][n] = W[n][k]

    int tid   = threadIdx.x;
    int m_blk = blockIdx.x * TM;
    int lrow  = tid >> 1;              // 0..127
    int lk0   = (tid & 1) * 8;         // 0 or 8
    int tm0   = (tid >> 4) * 8;        // 0..120
    int tn0   = (tid & 15) * 8;        // 0..120

    float acc[8][8];
#pragma unroll
    for (int i = 0; i < 8; i++)
#pragma unroll
        for (int j = 0; j < 8; j++) acc[i][j] = 0.0f;

    for (int kc = 0; kc < F; kc += TK) {
        float4 a0 = {0,0,0,0}, a1 = {0,0,0,0};
        int gm = m_blk + lrow;
        if (gm < N_NODES) {
            const float4* p = (const float4*)(H + (size_t)gm * F + kc + lk0);
            a0 = p[0]; a1 = p[1];
        }
        const float4* q = (const float4*)(W + (size_t)lrow * F + kc + lk0);
        float4 b0 = q[0], b1 = q[1];

        __syncthreads();   // previous tile's compute done
        sA[lk0 + 0][lrow] = a0.x; sA[lk0 + 1][lrow] = a0.y;
        sA[lk0 + 2][lrow] = a0.z; sA[lk0 + 3][lrow] = a0.w;
        sA[lk0 + 4][lrow] = a1.x; sA[lk0 + 5][lrow] = a1.y;
        sA[lk0 + 6][lrow] = a1.z; sA[lk0 + 7][lrow] = a1.w;
        sB[lk0 + 0][lrow] = b0.x; sB[lk0 + 1][lrow] = b0.y;
        sB[lk0 + 2][lrow] = b0.z; sB[lk0 + 3][lrow] = b0.w;
        sB[lk0 + 4][lrow] = b1.x; sB[lk0 + 5][lrow] = b1.y;
        sB[lk0 + 6][lrow] = b1.z; sB[lk0 + 7][lrow] = b1.w;
        __syncthreads();

#pragma unroll
        for (int kk = 0; kk < TK; kk++) {
            float4 av0 = *(const float4*)&sA[kk][tm0];
            float4 av1 = *(const float4*)&sA[kk][tm0 + 4];
            float4 bv0 = *(const float4*)&sB[kk][tn0];
            float4 bv1 = *(const float4*)&sB[kk][tn0 + 4];
            float a[8] = {av0.x, av0.y, av0.z, av0.w, av1.x, av1.y, av1.z, av1.w};
            float b[8] = {bv0.x, bv0.y, bv0.z, bv0.w, bv1.x, bv1.y, bv1.z, bv1.w};
#pragma unroll
            for (int i = 0; i < 8; i++)
#pragma unroll
                for (int j = 0; j < 8; j++) acc[i][j] += a[i] * b[j];
        }
    }

    float bj[8];
#pragma unroll
    for (int j = 0; j < 8; j++) bj[j] = __ldg(&bias[tn0 + j]);

#pragma unroll
    for (int i = 0; i < 8; i++) {
#pragma unroll
        for (int j = 0; j < 8; j++) acc[i][j] += bj[j];
    }

    // fused log_softmax per row, half-warp (16-lane) reductions
#pragma unroll
    for (int i = 0; i < 8; i++) {
        float m = acc[i][0];
#pragma unroll
        for (int j = 1; j < 8; j++) m = fmaxf(m, acc[i][j]);
#pragma unroll
        for (int o = 1; o < 16; o <<= 1)
            m = fmaxf(m, __shfl_xor_sync(0xFFFFFFFFu, m, o));

        float s = 0.0f;
#pragma unroll
        for (int j = 0; j < 8; j++) s += expf(acc[i][j] - m);
#pragma unroll
        for (int o = 1; o < 16; o <<= 1)
            s += __shfl_xor_sync(0xFFFFFFFFu, s, o);

        float l = m + logf(s);
#pragma unroll
        for (int j = 0; j < 8; j++) acc[i][j] -= l;
    }

#pragma unroll
    for (int i = 0; i < 8; i++) {
        int gm = m_blk + tm0 + i;
        if (gm < N_NODES) {
            float4 o0, o1;
            o0.x = acc[i][0]; o0.y = acc[i][1]; o0.z = acc[i][2]; o0.w = acc[i][3];
            o1.x = acc[i][4]; o1.y = acc[i][5]; o1.z = acc[i][6]; o1.w = acc[i][7];
            float* op = out + (size_t)gm * F + tn0;
            ((float4*)op)[0] = o0;
            ((float4*)op)[1] = o1;
        }
    }
}

// ---------------- launch ----------------
extern "C" void kernel_launch(void* const* d_in, const int* in_sizes, int n_in,
                              void* d_out, int out_size) {
    const float* x  = (const float*)d_in[0];   // [100000, 128]
    const float* W  = (const float*)d_in[1];   // [128, 128]
    const float* b  = (const float*)d_in[2];   // [128]
    const int*   ei = (const int*)d_in[3];     // [2, 800000] as int32
    float* out = (float*)d_out;

    float* h1;  cudaGetSymbolAddress((void**)&h1, g_h1);
    float* h2;  cudaGetSymbolAddress((void**)&h2, g_h2);
    int*   deg; cudaGetSymbolAddress((void**)&deg, g_deg);

    const int nodes_b = (N_NODES + 255) / 256;
    const int edges_b = (N_EDGES + 255) / 256;
    const int warp_b  = (N_NODES * 32 + 255) / 256;
    const int gemm_b  = (N_NODES + TM - 1) / TM;

    cudaMemsetAsync(deg, 0, N_NODES * sizeof(int));
    k_count<<<edges_b, 256>>>(ei);
    k_scan1<<<NB_SCAN, SCAN_B>>>();
    k_scan2<<<1, 128>>>();
    k_scan3<<<nodes_b, 256>>>();
    k_place<<<edges_b, 256>>>(ei);

    k_hop<<<warp_b, 256>>>(x, h1);
    k_hop<<<warp_b, 256>>>(h1, h2);

    k_gemm_lsm<<<gemm_b, 256>>>(h2, W, b, out);
}

// round 7
// speedup vs baseline: 1.7108x; 1.0870x over previous
#include <cuda_runtime.h>
#include <math.h>

#define N_NODES 100000
#define N_EDGES 800000
#define F 128
#define SCAN_B 1024
#define NB_SCAN ((N_NODES + SCAN_B - 1) / SCAN_B)   // 98

// ---------------- static scratch (allocation-free rule) ----------------
__device__ int   g_deg[N_NODES];
__device__ float g_dinv[N_NODES];
__device__ int   g_off[N_NODES + 1];
__device__ int   g_cursor[N_NODES];
__device__ int   g_src[N_EDGES];
__device__ int   g_bsum[NB_SCAN + 32];
__device__ float g_h1[(size_t)N_NODES * F];
__device__ float g_h2[(size_t)N_NODES * F];

// ---------------- degree count ----------------
__global__ void k_count(const int* __restrict__ ei) {
    int e = blockIdx.x * blockDim.x + threadIdx.x;
    if (e < N_EDGES) {
        int col = ei[N_EDGES + e];
        if ((unsigned)col < (unsigned)N_NODES)
            atomicAdd(&g_deg[col], 1);
    }
}

// ---------------- exclusive scan of g_deg -> g_off ----------------
__global__ void k_scan1() {
    __shared__ int s[SCAN_B];
    int i = blockIdx.x * SCAN_B + threadIdx.x;
    int v = (i < N_NODES) ? g_deg[i] : 0;
    s[threadIdx.x] = v;
    __syncthreads();
    for (int off = 1; off < SCAN_B; off <<= 1) {
        int t = 0;
        if (threadIdx.x >= off) t = s[threadIdx.x - off];
        __syncthreads();
        if (threadIdx.x >= off) s[threadIdx.x] += t;
        __syncthreads();
    }
    if (i < N_NODES) g_off[i] = s[threadIdx.x] - v;  // partial exclusive
    if (threadIdx.x == SCAN_B - 1) g_bsum[blockIdx.x] = s[threadIdx.x];
}

// parallel scan of the 98 block sums (one block, Hillis-Steele)
__global__ void k_scan2() {
    __shared__ int s[128];
    int t = threadIdx.x;
    int v = (t < NB_SCAN) ? g_bsum[t] : 0;
    s[t] = v;
    __syncthreads();
#pragma unroll
    for (int off = 1; off < 128; off <<= 1) {
        int u = 0;
        if (t >= off) u = s[t - off];
        __syncthreads();
        if (t >= off) s[t] += u;
        __syncthreads();
    }
    if (t < NB_SCAN) g_bsum[t] = s[t] - v;  // exclusive
}

__global__ void k_scan3() {
    int i = blockIdx.x * blockDim.x + threadIdx.x;
    if (i < N_NODES) {
        int off = g_off[i] + g_bsum[i / SCAN_B];
        g_off[i] = off;
        g_cursor[i] = off;
        // dinv: degree includes self loop (+1)
        g_dinv[i] = rsqrtf((float)(g_deg[i] + 1));
    }
    if (i == 0) g_off[N_NODES] = N_EDGES;
}

// ---------------- place edges into CSR (by destination) ----------------
__global__ void k_place(const int* __restrict__ ei) {
    int e = blockIdx.x * blockDim.x + threadIdx.x;
    if (e < N_EDGES) {
        int row = ei[e];
        int col = ei[N_EDGES + e];
        if ((unsigned)row < (unsigned)N_NODES && (unsigned)col < (unsigned)N_NODES) {
            int pos = atomicAdd(&g_cursor[col], 1);
            if ((unsigned)pos < (unsigned)N_EDGES)
                g_src[pos] = row;
        }
    }
}

// ---------------- one propagation hop (gather form, warp per node) ----------------
__global__ void k_hop(const float* __restrict__ hin, float* __restrict__ hout) {
    int gt   = blockIdx.x * blockDim.x + threadIdx.x;
    int node = gt >> 5;
    int lane = gt & 31;
    if (node >= N_NODES) return;

    float di = __ldg(&g_dinv[node]);
    const float4* hin4 = (const float4*)hin;

    // self loop: weight dinv[i]^2 ; edges: dinv[i]*dinv[src]
    float4 v = __ldg(&hin4[(size_t)node * 32 + lane]);
    float4 acc;
    acc.x = di * v.x; acc.y = di * v.y; acc.z = di * v.z; acc.w = di * v.w;

    int s = __ldg(&g_off[node]);
    int e = __ldg(&g_off[node + 1]);
    int k = s;
    // 4-wide software pipeline: issue all index/weight/row loads before
    // consuming -> 4x outstanding 512B row loads per warp.
    for (; k + 3 < e; k += 4) {
        int s0 = __ldg(&g_src[k]);
        int s1 = __ldg(&g_src[k + 1]);
        int s2 = __ldg(&g_src[k + 2]);
        int s3 = __ldg(&g_src[k + 3]);
        float w0 = __ldg(&g_dinv[s0]);
        float w1 = __ldg(&g_dinv[s1]);
        float w2 = __ldg(&g_dinv[s2]);
        float w3 = __ldg(&g_dinv[s3]);
        float4 u0 = __ldg(&hin4[(size_t)s0 * 32 + lane]);
        float4 u1 = __ldg(&hin4[(size_t)s1 * 32 + lane]);
        float4 u2 = __ldg(&hin4[(size_t)s2 * 32 + lane]);
        float4 u3 = __ldg(&hin4[(size_t)s3 * 32 + lane]);
        acc.x += w0 * u0.x + w1 * u1.x + w2 * u2.x + w3 * u3.x;
        acc.y += w0 * u0.y + w1 * u1.y + w2 * u2.y + w3 * u3.y;
        acc.z += w0 * u0.z + w1 * u1.z + w2 * u2.z + w3 * u3.z;
        acc.w += w0 * u0.w + w1 * u1.w + w2 * u2.w + w3 * u3.w;
    }
    for (; k < e; k++) {
        int s0 = __ldg(&g_src[k]);
        float w0 = __ldg(&g_dinv[s0]);
        float4 u0 = __ldg(&hin4[(size_t)s0 * 32 + lane]);
        acc.x += w0 * u0.x; acc.y += w0 * u0.y;
        acc.z += w0 * u0.z; acc.w += w0 * u0.w;
    }
    acc.x *= di; acc.y *= di; acc.z *= di; acc.w *= di;
    ((float4*)hout)[(size_t)node * 32 + lane] = acc;
}

// ---------------- GEMM + fused log_softmax, packed f32x2 FMA ----------------
// out[n][o] = log_softmax_o( sum_k H[n][k]*W[o][k] + b[o] )
// Inner product uses Blackwell fma.rn.f32x2 (2 fp32 FMAs per fma-pipe op):
// accumulators are 8x4 packed pairs; b-pairs load directly from smem as 64-bit;
// a is duplicated into both halves with one mov.b64 per element.
#define TM 128
#define TN 128
#define TK 16

__global__ __launch_bounds__(256) void k_gemm_lsm(const float* __restrict__ H,
                                                  const float* __restrict__ W,
                                                  const float* __restrict__ bias,
                                                  float* __restrict__ out) {
    __shared__ float sA[TK][TM];   // sA[k][m]
    __shared__ float sB[TK][TN];   // sB[k][n] = W[n][k]

    int tid   = threadIdx.x;
    int m_blk = blockIdx.x * TM;
    int lrow  = tid >> 1;              // 0..127
    int lk0   = (tid & 1) * 8;         // 0 or 8
    int tm0   = (tid >> 4) * 8;        // 0..120
    int tn0   = (tid & 15) * 8;        // 0..120

    unsigned long long acc2[8][4];     // acc2[i][j] = (acc[i][2j], acc[i][2j+1])
#pragma unroll
    for (int i = 0; i < 8; i++)
#pragma unroll
        for (int j = 0; j < 4; j++) acc2[i][j] = 0ULL;

    for (int kc = 0; kc < F; kc += TK) {
        float4 a0 = {0,0,0,0}, a1 = {0,0,0,0};
        int gm = m_blk + lrow;
        if (gm < N_NODES) {
            const float4* p = (const float4*)(H + (size_t)gm * F + kc + lk0);
            a0 = p[0]; a1 = p[1];
        }
        const float4* q = (const float4*)(W + (size_t)lrow * F + kc + lk0);
        float4 b0 = q[0], b1 = q[1];

        __syncthreads();   // previous tile's compute done
        sA[lk0 + 0][lrow] = a0.x; sA[lk0 + 1][lrow] = a0.y;
        sA[lk0 + 2][lrow] = a0.z; sA[lk0 + 3][lrow] = a0.w;
        sA[lk0 + 4][lrow] = a1.x; sA[lk0 + 5][lrow] = a1.y;
        sA[lk0 + 6][lrow] = a1.z; sA[lk0 + 7][lrow] = a1.w;
        sB[lk0 + 0][lrow] = b0.x; sB[lk0 + 1][lrow] = b0.y;
        sB[lk0 + 2][lrow] = b0.z; sB[lk0 + 3][lrow] = b0.w;
        sB[lk0 + 4][lrow] = b1.x; sB[lk0 + 5][lrow] = b1.y;
        sB[lk0 + 6][lrow] = b1.z; sB[lk0 + 7][lrow] = b1.w;
        __syncthreads();

#pragma unroll
        for (int kk = 0; kk < TK; kk++) {
            float4 av0 = *(const float4*)&sA[kk][tm0];
            float4 av1 = *(const float4*)&sA[kk][tm0 + 4];
            ulonglong2 bq0 = *(const ulonglong2*)&sB[kk][tn0];      // (b0,b1),(b2,b3)
            ulonglong2 bq1 = *(const ulonglong2*)&sB[kk][tn0 + 4];  // (b4,b5),(b6,b7)
            unsigned long long bp[4] = {bq0.x, bq0.y, bq1.x, bq1.y};
            float a[8] = {av0.x, av0.y, av0.z, av0.w, av1.x, av1.y, av1.z, av1.w};
#pragma unroll
            for (int i = 0; i < 8; i++) {
                unsigned long long ap;
                unsigned int ar = __float_as_uint(a[i]);
                asm("mov.b64 %0, {%1, %1};" : "=l"(ap) : "r"(ar));
#pragma unroll
                for (int j = 0; j < 4; j++) {
                    asm("fma.rn.f32x2 %0, %1, %2, %0;"
                        : "+l"(acc2[i][j]) : "l"(ap), "l"(bp[j]));
                }
            }
        }
    }

    // unpack accumulators
    float acc[8][8];
#pragma unroll
    for (int i = 0; i < 8; i++)
#pragma unroll
        for (int j = 0; j < 4; j++) {
            unsigned int lo, hi;
            asm("mov.b64 {%0, %1}, %2;" : "=r"(lo), "=r"(hi) : "l"(acc2[i][j]));
            acc[i][2 * j]     = __uint_as_float(lo);
            acc[i][2 * j + 1] = __uint_as_float(hi);
        }

    float bj[8];
#pragma unroll
    for (int j = 0; j < 8; j++) bj[j] = __ldg(&bias[tn0 + j]);

#pragma unroll
    for (int i = 0; i < 8; i++) {
#pragma unroll
        for (int j = 0; j < 8; j++) acc[i][j] += bj[j];
    }

    // fused log_softmax per row, half-warp (16-lane) reductions
#pragma unroll
    for (int i = 0; i < 8; i++) {
        float m = acc[i][0];
#pragma unroll
        for (int j = 1; j < 8; j++) m = fmaxf(m, acc[i][j]);
#pragma unroll
        for (int o = 1; o < 16; o <<= 1)
            m = fmaxf(m, __shfl_xor_sync(0xFFFFFFFFu, m, o));

        float s = 0.0f;
#pragma unroll
        for (int j = 0; j < 8; j++) s += expf(acc[i][j] - m);
#pragma unroll
        for (int o = 1; o < 16; o <<= 1)
            s += __shfl_xor_sync(0xFFFFFFFFu, s, o);

        float l = m + logf(s);
#pragma unroll
        for (int j = 0; j < 8; j++) acc[i][j] -= l;
    }

#pragma unroll
    for (int i = 0; i < 8; i++) {
        int gm = m_blk + tm0 + i;
        if (gm < N_NODES) {
            float4 o0, o1;
            o0.x = acc[i][0]; o0.y = acc[i][1]; o0.z = acc[i][2]; o0.w = acc[i][3];
            o1.x = acc[i][4]; o1.y = acc[i][5]; o1.z = acc[i][6]; o1.w = acc[i][7];
            float* op = out + (size_t)gm * F + tn0;
            ((float4*)op)[0] = o0;
            ((float4*)op)[1] = o1;
        }
    }
}

// ---------------- launch ----------------
extern "C" void kernel_launch(void* const* d_in, const int* in_sizes, int n_in,
                              void* d_out, int out_size) {
    const float* x  = (const float*)d_in[0];   // [100000, 128]
    const float* W  = (const float*)d_in[1];   // [128, 128]
    const float* b  = (const float*)d_in[2];   // [128]
    const int*   ei = (const int*)d_in[3];     // [2, 800000] as int32
    float* out = (float*)d_out;

    float* h1;  cudaGetSymbolAddress((void**)&h1, g_h1);
    float* h2;  cudaGetSymbolAddress((void**)&h2, g_h2);
    int*   deg; cudaGetSymbolAddress((void**)&deg, g_deg);

    const int nodes_b = (N_NODES + 255) / 256;
    const int edges_b = (N_EDGES + 255) / 256;
    const int warp_b  = (N_NODES * 32 + 255) / 256;
    const int gemm_b  = (N_NODES + TM - 1) / TM;

    cudaMemsetAsync(deg, 0, N_NODES * sizeof(int));
    k_count<<<edges_b, 256>>>(ei);
    k_scan1<<<NB_SCAN, SCAN_B>>>();
    k_scan2<<<1, 128>>>();
    k_scan3<<<nodes_b, 256>>>();
    k_place<<<edges_b, 256>>>(ei);

    k_hop<<<warp_b, 256>>>(x, h1);
    k_hop<<<warp_b, 256>>>(h1, h2);

    k_gemm_lsm<<<gemm_b, 256>>>(h2, W, b, out);
}